// round 16
// baseline (speedup 1.0000x reference)
#include <cuda_runtime.h>
#include <cuda_bf16.h>
#include <cstdint>

// Problem constants
#define B_  4
#define C_  256
#define H_  64
#define W_  64
#define O_  256
#define K2_ 9
#define PAD_ 2
#define DIL_ 2
#define CK_ (C_ * K2_)            // 2304
#define HW_ (H_ * W_)             // 4096
#define OUT_MAIN (B_ * O_ * HW_)  // 4194304
#define DW_ELEMS (O_ * C_ * K2_)  // 589824

#define SWZ(off) ((off) ^ (((off) >> 3) & 0x70))

// ---------------------------------------------------------------------------
// Scratch (device globals; no allocation allowed)
// ---------------------------------------------------------------------------
__device__ float g_off[B_ * 18 * HW_];            // clipped offsets (B,18,H,W)
__device__ float g_xT[B_ * HW_ * C_];             // x transposed: [b][hw][c]
__device__ unsigned char g_w[36 * 65536];         // bf16 hi/lo weight tiles, pre-swizzled

// ---------------------------------------------------------------------------
// helpers
// ---------------------------------------------------------------------------
__device__ __forceinline__ void ldsm4(uint32_t* r, uint32_t addr) {
    asm volatile("ldmatrix.sync.aligned.m8n8.x4.shared.b16 {%0,%1,%2,%3}, [%4];"
        : "=r"(r[0]), "=r"(r[1]), "=r"(r[2]), "=r"(r[3]) : "r"(addr));
}
__device__ __forceinline__ void mma16816(float* c, const uint32_t* a, const uint32_t* b) {
    asm volatile("mma.sync.aligned.m16n8k16.row.col.f32.bf16.bf16.f32 "
        "{%0,%1,%2,%3}, {%4,%5,%6,%7}, {%8,%9}, {%0,%1,%2,%3};"
        : "+f"(c[0]), "+f"(c[1]), "+f"(c[2]), "+f"(c[3])
        : "r"(a[0]), "r"(a[1]), "r"(a[2]), "r"(a[3]), "r"(b[0]), "r"(b[1]));
}
__device__ __forceinline__ uint32_t smem_u32(const void* p) {
    uint32_t a;
    asm("{ .reg .u64 t; cvta.to.shared.u64 t, %1; cvt.u32.u64 %0, t; }"
        : "=r"(a) : "l"(p));
    return a;
}
__device__ __forceinline__ uint32_t pack_bf16(float a, float b) {
    return ((uint32_t)__bfloat16_as_ushort(__float2bfloat16(b)) << 16) |
           (uint32_t)__bfloat16_as_ushort(__float2bfloat16(a));
}
__device__ __forceinline__ void cpasync16(uint32_t dst, const void* src) {
    asm volatile("cp.async.cg.shared.global [%0], [%1], 16;"
        :: "r"(dst), "l"(src) : "memory");
}

// ---------------------------------------------------------------------------
// Merged prologue kernel: roles by blockIdx.x (all 256 threads).
//   [0,128)       : OFFSET CONV AS TENSOR-CORE GEMM -> g_off
//                   block = (b, h2) 128 px; M=32 (18 used), K=2304 in 36 chunks
//   [128,4224)    : transpose x -> g_xT (32x32 tiles)
//   [4224,6528)   : weight prep (bf16 hi/lo, pre-swizzled) + tail copy
// ---------------------------------------------------------------------------
#define NB_OG 128
#define NB_T  4096
#define NB_P  2304
#define PRO_SMEM 41472
// offset-GEMM smem layout (bytes inside dynamic sm):
//   A hi [0,4096), A lo [4096,8192)        (32 rows x 64 bf16, SW128)
//   B hi [8192,24576), B lo [24576,40960)  (128 rows x 64 bf16, SW128)

__global__ __launch_bounds__(256) void prologue_kernel(
    const float* __restrict__ x, const float* __restrict__ ow,
    const float* __restrict__ ob, const float* __restrict__ dw,
    float* __restrict__ out_tail)
{
    extern __shared__ float sm[];
    const int bid = blockIdx.x;
    const int tid = threadIdx.x;

    if (bid < NB_OG) {
        // ---- offset conv via bf16-split MMA ----
        char* smc = (char*)sm;
        const uint32_t sb = smem_u32(sm);
        const int b  = bid >> 5;
        const int h2 = bid & 31;
        const int wid = tid >> 5;
        const int lid = tid & 31;

        const int mt    = wid & 1;            // m-tile (rows mt*16..+15)
        const int nbase = (wid >> 1) * 32;    // 32-px region
        const int aRow = mt * 16 + (lid & 15);
        const int aKad = (lid >> 4) * 16;
        const int bRow = nbase + ((lid >> 4) & 1) * 8 + (lid & 7);
        const int bKad = ((lid >> 3) & 1) * 16;

        float acc[4][4];
#pragma unroll
        for (int j = 0; j < 4; j++)
#pragma unroll
            for (int q = 0; q < 4; q++) acc[j][q] = 0.0f;

        for (int t = 0; t < 36; t++) {
            const int n  = t >> 2;
            const int c0 = (t & 3) * 64;
            const int dy = n / 3 - 1;
            const int dx = n % 3 - 1;
            __syncthreads();

            // stage A: 32 rows x 64 k (rows >=18 zero; only write zeros once)
            for (int i = tid; i < 2048; i += 256) {
                int row = i >> 6;
                int kk  = i & 63;
                uint32_t sw = SWZ((uint32_t)(row * 128 + kk * 2));
                if (row < 18) {
                    float v = __ldg(ow + row * CK_ + (c0 + kk) * 9 + n);
                    __nv_bfloat16 hi = __float2bfloat16(v);
                    __nv_bfloat16 lo = __float2bfloat16(v - __bfloat162float(hi));
                    *(__nv_bfloat16*)(smc + sw)        = hi;
                    *(__nv_bfloat16*)(smc + 4096 + sw) = lo;
                } else if (t == 0) {
                    *(__nv_bfloat16*)(smc + sw)        = __float2bfloat16(0.f);
                    *(__nv_bfloat16*)(smc + 4096 + sw) = __float2bfloat16(0.f);
                }
            }
            // stage B: im2col, lanes along pixels (coalesced reads from x)
#pragma unroll
            for (int it = 0; it < 8; it++) {
                int id = tid + it * 256;
                int p  = id & 127;
                int c4 = (id >> 7) & 15;
                int h = h2 * 2 + (p >> 6);
                int w = p & 63;
                int yy = h + dy, xx = w + dx;
                bool ok = (yy >= 0) & (yy < H_) & (xx >= 0) & (xx < W_);
                const float* xp = x + ((size_t)b * C_ + c0 + c4 * 4) * HW_
                                    + yy * W_ + xx;
                float s0 = ok ? __ldg(xp)            : 0.f;
                float s1 = ok ? __ldg(xp + HW_)      : 0.f;
                float s2 = ok ? __ldg(xp + 2 * HW_)  : 0.f;
                float s3 = ok ? __ldg(xp + 3 * HW_)  : 0.f;
                uint32_t h0 = pack_bf16(s0, s1), h1 = pack_bf16(s2, s3);
                float r0 = s0 - __bfloat162float(__float2bfloat16(s0));
                float r1 = s1 - __bfloat162float(__float2bfloat16(s1));
                float r2 = s2 - __bfloat162float(__float2bfloat16(s2));
                float r3 = s3 - __bfloat162float(__float2bfloat16(s3));
                uint32_t l0 = pack_bf16(r0, r1), l1 = pack_bf16(r2, r3);
                uint32_t sw = SWZ((uint32_t)(p * 128 + c4 * 8));
                *(uint2*)(smc + 8192  + sw) = make_uint2(h0, h1);
                *(uint2*)(smc + 24576 + sw) = make_uint2(l0, l1);
            }
            __syncthreads();

            // MMA: 4 ksteps x (Ah*Bh + Ah*Bl + Al*Bh)
#pragma unroll
            for (int ks = 0; ks < 4; ks++) {
                uint32_t bh[8], bl[8];
#pragma unroll
                for (int pair = 0; pair < 2; pair++) {
                    uint32_t off = SWZ((uint32_t)((bRow + pair * 16) * 128 + ks * 32 + bKad));
                    ldsm4(bh + pair * 4, sb + 8192  + off);
                    ldsm4(bl + pair * 4, sb + 24576 + off);
                }
                uint32_t offA = SWZ((uint32_t)(aRow * 128 + ks * 32 + aKad));
                uint32_t ah[4], al[4];
                ldsm4(ah, sb + offA);
                ldsm4(al, sb + 4096 + offA);
#pragma unroll
                for (int j = 0; j < 4; j++) {
                    mma16816(acc[j], ah, bh + j * 2);
                    mma16816(acc[j], ah, bl + j * 2);
                    mma16816(acc[j], al, bh + j * 2);
                }
            }
        }

        // epilogue: bias + clip -> g_off (rows >= 18 discarded)
#pragma unroll
        for (int j = 0; j < 4; j++) {
#pragma unroll
            for (int q = 0; q < 4; q++) {
                int ch = mt * 16 + (lid >> 2) + ((q >> 1) * 8);
                int px = nbase + j * 8 + (lid & 3) * 2 + (q & 1);
                if (ch < 18) {
                    float s = acc[j][q] + __ldg(ob + ch);
                    s = fminf(fmaxf(s, -1.0f), 1.0f);
                    g_off[((size_t)b * 18 + ch) * HW_
                          + (h2 * 2 + (px >> 6)) * W_ + (px & 63)] = s;
                }
            }
        }
        return;
    }

    if (bid < NB_OG + NB_T) {
        // ---- transpose ----
        __shared__ float ts[32][33];
        const int tb = bid - NB_OG;
        const int b = tb >> 10;
        const int tile = tb & 1023;
        const int c0 = (tile >> 7) * 32;
        const int hw0 = (tile & 127) * 32;
        const int tx = tid & 31, ty = tid >> 5;
        const float* xb = x + (size_t)b * C_ * HW_;
#pragma unroll
        for (int i = 0; i < 4; i++)
            ts[ty + i * 8][tx] = __ldg(xb + (size_t)(c0 + ty + i * 8) * HW_ + hw0 + tx);
        __syncthreads();
        float* dst = g_xT + (size_t)b * HW_ * C_;
#pragma unroll
        for (int i = 0; i < 4; i++)
            dst[(size_t)(hw0 + ty + i * 8) * C_ + c0 + tx] = ts[tx][ty + i * 8];
        return;
    }

    // ---- weight prep + tail copy ----
    {
        int id = (bid - NB_OG - NB_T) * 256 + tid;
        out_tail[id] = dw[id];
        int k = id & 63;
        int o = (id >> 6) & 255;
        int t = id >> 14;            // 0..35
        int n = t >> 2;
        int cc = t & 3;
        int c = cc * 64 + k;
        float v = __ldg(dw + o * CK_ + c * 9 + n);
        __nv_bfloat16 hi = __float2bfloat16(v);
        __nv_bfloat16 lo = __float2bfloat16(v - __bfloat162float(hi));
        uint32_t sw = SWZ((uint32_t)(o * 128 + k * 2));
        size_t base = (size_t)t * 65536;
        *(__nv_bfloat16*)(g_w + base + sw)         = hi;
        *(__nv_bfloat16*)(g_w + base + 32768 + sw) = lo;
    }
}

// ---------------------------------------------------------------------------
// Fused deform sampling + bf16-split mma.sync GEMM, software pipelined.
// (byte-exact R6 winner: 16 warps, warp tile 64x32, double-buffered A+B)
// ---------------------------------------------------------------------------
#define OFF_A    0        // 2 buf x [2 comp][256][64] bf16 = 2 x 65536
#define OFF_B    131072   // 2 buf x [2 comp][128][64] bf16 = 2 x 32768
#define OFF_SWT  196608   // float [9*128][4]  = 18432
#define OFF_SIDX 215040   // short [9*128][4]  = 9216
#define FUSED_SMEM 224256

__global__ __launch_bounds__(512, 1) void fused_deform_mma_kernel(
    const float* __restrict__ db, float* __restrict__ out)
{
    extern __shared__ char smem[];
    const uint32_t sb = smem_u32(smem);
    const int tid = threadIdx.x;
    const int wid = tid >> 5;
    const int lid = tid & 31;
    const int b  = blockIdx.x >> 5;
    const int h2 = blockIdx.x & 31;

    // ---- sampling metadata: 9 taps x 128 pixels ----
    float* swt  = (float*)(smem + OFF_SWT);
    short* sidx = (short*)(smem + OFF_SIDX);
    for (int task = tid; task < 9 * 128; task += 512) {
        int n = task >> 7;
        int p = task & 127;
        int h = h2 * 2 + (p >> 6);
        int w = p & 63;
        float dy = g_off[((size_t)b * 18 + 2 * n)     * HW_ + h * W_ + w];
        float dx = g_off[((size_t)b * 18 + 2 * n + 1) * HW_ + h * W_ + w];
        float py = dy + (float)(-PAD_ + (n / 3) * DIL_ + h);
        float px = dx + (float)(-PAD_ + (n % 3) * DIL_ + w);
        float y0f = floorf(py);
        float x0f = floorf(px);
        float ly1 = py - y0f, lx1 = px - x0f;
        float ly0 = 1.0f - ly1, lx0 = 1.0f - lx1;
        int y0 = (int)y0f, x0 = (int)x0f;
#pragma unroll
        for (int j = 0; j < 4; j++) {
            int yy = y0 + (j >> 1);
            int xx = x0 + (j & 1);
            float wgt = ((j >> 1) ? ly1 : ly0) * ((j & 1) ? lx1 : lx0);
            bool ok = (yy >= 0) & (yy < H_) & (xx >= 0) & (xx < W_);
            int yi = min(max(yy, 0), H_ - 1);
            int xi = min(max(xx, 0), W_ - 1);
            sidx[task * 4 + j] = (short)(yi * W_ + xi);
            swt [task * 4 + j] = ok ? wgt : 0.0f;
        }
    }
    __syncthreads();

    const float* xT = g_xT + (size_t)b * HW_ * C_;
    const int ch4 = tid & 15;          // channel group of 4 (fixed per thread)
    const int pixB = tid >> 4;         // base pixel selector

    const int wm = wid >> 2;           // 0..3 : o block of 64
    const int wn = wid & 3;            // 0..3 : pixel block of 32
    const int aRow = wm * 64 + (lid & 15);
    const int aKad = (lid >> 4) * 16;
    const int bRow = wn * 32 + ((lid >> 4) & 1) * 8 + (lid & 7);
    const int bKad = ((lid >> 3) & 1) * 16;

    float acc[4][4][4];
#pragma unroll
    for (int i = 0; i < 4; i++)
#pragma unroll
        for (int j = 0; j < 4; j++)
#pragma unroll
            for (int q = 0; q < 4; q++) acc[i][j][q] = 0.0f;

    // ---- prologue: stage chunk 0 ----
    {
        uint32_t dstA = sb + OFF_A;
        const char* srcA = (const char*)g_w;
#pragma unroll
        for (int i = 0; i < 8; i++)
            cpasync16(dstA + (tid + i * 512) * 16, srcA + (size_t)(tid + i * 512) * 16);
        asm volatile("cp.async.commit_group;" ::: "memory");
#pragma unroll
        for (int ph = 0; ph < 4; ph++) {
            int id = tid + ph * 512;
            int c4 = id & 15;
            int p  = id >> 4;
            const float4 wt = *(const float4*)(swt + p * 4);
            const short* si = sidx + p * 4;
            const float* xb = xT + c4 * 4;
            float4 v0 = __ldg((const float4*)(xb + ((int)si[0] << 8)));
            float4 v1 = __ldg((const float4*)(xb + ((int)si[1] << 8)));
            float4 v2 = __ldg((const float4*)(xb + ((int)si[2] << 8)));
            float4 v3 = __ldg((const float4*)(xb + ((int)si[3] << 8)));
            float s0 = wt.x * v0.x + wt.y * v1.x + wt.z * v2.x + wt.w * v3.x;
            float s1 = wt.x * v0.y + wt.y * v1.y + wt.z * v2.y + wt.w * v3.y;
            float s2 = wt.x * v0.z + wt.y * v1.z + wt.z * v2.z + wt.w * v3.z;
            float s3 = wt.x * v0.w + wt.y * v1.w + wt.z * v2.w + wt.w * v3.w;
            uint32_t h0 = pack_bf16(s0, s1), h1 = pack_bf16(s2, s3);
            float r0 = s0 - __bfloat162float(__float2bfloat16(s0));
            float r1 = s1 - __bfloat162float(__float2bfloat16(s1));
            float r2 = s2 - __bfloat162float(__float2bfloat16(s2));
            float r3 = s3 - __bfloat162float(__float2bfloat16(s3));
            uint32_t l0 = pack_bf16(r0, r1), l1 = pack_bf16(r2, r3);
            uint32_t sw = SWZ((uint32_t)(p * 128 + c4 * 8));
            *(uint2*)(smem + OFF_B + sw)         = make_uint2(h0, h1);
            *(uint2*)(smem + OFF_B + 16384 + sw) = make_uint2(l0, l1);
        }
    }

    for (int t = 0; t < 36; t++) {
        const uint32_t bufT = (uint32_t)(t & 1);
        const uint32_t bufN = bufT ^ 1;
        const bool more = (t < 35);

        // bar1: all reads of buffer bufN's OLD content complete
        __syncthreads();

        if (more) {
            uint32_t dstA = sb + OFF_A + bufN * 65536;
            const char* srcA = (const char*)(g_w + (size_t)(t + 1) * 65536);
#pragma unroll
            for (int i = 0; i < 8; i++)
                cpasync16(dstA + (tid + i * 512) * 16, srcA + (size_t)(tid + i * 512) * 16);
            asm volatile("cp.async.commit_group;" ::: "memory");
            asm volatile("cp.async.wait_group 1;" ::: "memory");
        } else {
            asm volatile("cp.async.wait_group 0;" ::: "memory");
        }

        // bar2: everyone's A(t) landed; B(t) STS from iter t-1 visible
        __syncthreads();

        const uint32_t aBaseH = sb + OFF_A + bufT * 65536;
        const uint32_t aBaseL = aBaseH + 32768;
        const uint32_t bBaseH = sb + OFF_B + bufT * 32768;
        const uint32_t bBaseL = bBaseH + 16384;
        char* bDst = smem + OFF_B + bufN * 32768;

        const int nN = (t + 1) >> 2;
        const int cN = ((t + 1) & 3) * 64;

#pragma unroll
        for (int ph = 0; ph < 4; ph++) {
            float4 v0, v1, v2, v3; float4 wt;
            int p = (pixB + ph * 32) & 127;
            if (more) {
                int task = nN * 128 + p;
                wt = *(const float4*)(swt + task * 4);
                const short* si = sidx + task * 4;
                const float* xb = xT + cN + ch4 * 4;
                v0 = __ldg((const float4*)(xb + ((int)si[0] << 8)));
                v1 = __ldg((const float4*)(xb + ((int)si[1] << 8)));
                v2 = __ldg((const float4*)(xb + ((int)si[2] << 8)));
                v3 = __ldg((const float4*)(xb + ((int)si[3] << 8)));
            }

            // MMA k-step ph of chunk t
            {
                uint32_t bh[8], bl[8];
#pragma unroll
                for (int pair = 0; pair < 2; pair++) {
                    uint32_t off = SWZ((uint32_t)((bRow + pair * 16) * 128 + ph * 32 + bKad));
                    ldsm4(bh + pair * 4, bBaseH + off);
                    ldsm4(bl + pair * 4, bBaseL + off);
                }
#pragma unroll
                for (int mt = 0; mt < 4; mt++) {
                    uint32_t offA = SWZ((uint32_t)((aRow + mt * 16) * 128 + ph * 32 + aKad));
                    uint32_t ah[4], al[4];
                    ldsm4(ah, aBaseH + offA);
#pragma unroll
                    for (int j = 0; j < 4; j++) {
                        mma16816(acc[mt][j], ah, bh + j * 2);
                        mma16816(acc[mt][j], ah, bl + j * 2);
                    }
                    ldsm4(al, aBaseL + offA);
#pragma unroll
                    for (int j = 0; j < 4; j++)
                        mma16816(acc[mt][j], al, bh + j * 2);
                }
            }

            if (more) {
                float s0 = wt.x * v0.x + wt.y * v1.x + wt.z * v2.x + wt.w * v3.x;
                float s1 = wt.x * v0.y + wt.y * v1.y + wt.z * v2.y + wt.w * v3.y;
                float s2 = wt.x * v0.z + wt.y * v1.z + wt.z * v2.z + wt.w * v3.z;
                float s3 = wt.x * v0.w + wt.y * v1.w + wt.z * v2.w + wt.w * v3.w;
                uint32_t h0 = pack_bf16(s0, s1), h1 = pack_bf16(s2, s3);
                float r0 = s0 - __bfloat162float(__float2bfloat16(s0));
                float r1 = s1 - __bfloat162float(__float2bfloat16(s1));
                float r2 = s2 - __bfloat162float(__float2bfloat16(s2));
                float r3 = s3 - __bfloat162float(__float2bfloat16(s3));
                uint32_t l0 = pack_bf16(r0, r1), l1 = pack_bf16(r2, r3);
                uint32_t sw = SWZ((uint32_t)(p * 128 + ch4 * 8));
                *(uint2*)(bDst + sw)         = make_uint2(h0, h1);
                *(uint2*)(bDst + 16384 + sw) = make_uint2(l0, l1);
            }
        }
    }

    // ---- epilogue: bias + store ----
#pragma unroll
    for (int mt = 0; mt < 4; mt++) {
        int o0 = wm * 64 + mt * 16 + (lid >> 2);
        float b0v = __ldg(db + o0);
        float b1v = __ldg(db + o0 + 8);
#pragma unroll
        for (int j = 0; j < 4; j++) {
            int pixel = wn * 32 + j * 8 + (lid & 3) * 2;
            int row = pixel >> 6, col = pixel & 63;
            float* p0 = out + ((size_t)(b * O_ + o0)) * HW_
                            + (size_t)(h2 * 2 + row) * W_ + col;
            *(float2*)p0 = make_float2(acc[mt][j][0] + b0v, acc[mt][j][1] + b0v);
            float* p1 = p0 + (size_t)8 * HW_;
            *(float2*)p1 = make_float2(acc[mt][j][2] + b1v, acc[mt][j][3] + b1v);
        }
    }
}

// ---------------------------------------------------------------------------
extern "C" void kernel_launch(void* const* d_in, const int* in_sizes, int n_in,
                              void* d_out, int out_size)
{
    const float* x  = (const float*)d_in[0];
    const float* ow = (const float*)d_in[1];
    const float* ob = (const float*)d_in[2];
    const float* dw = (const float*)d_in[3];
    const float* db = (const float*)d_in[4];
    float* out = (float*)d_out;

    cudaFuncSetAttribute(prologue_kernel,
                         cudaFuncAttributeMaxDynamicSharedMemorySize, PRO_SMEM);
    cudaFuncSetAttribute(fused_deform_mma_kernel,
                         cudaFuncAttributeMaxDynamicSharedMemorySize, FUSED_SMEM);

    prologue_kernel<<<NB_OG + NB_T + NB_P, 256, PRO_SMEM>>>(x, ow, ob, dw, out + OUT_MAIN);
    fused_deform_mma_kernel<<<B_ * 32, 512, FUSED_SMEM>>>(db, out);
}

// round 17
// speedup vs baseline: 1.1724x; 1.1724x over previous
#include <cuda_runtime.h>
#include <cuda_bf16.h>
#include <cstdint>

// Problem constants
#define B_  4
#define C_  256
#define H_  64
#define W_  64
#define O_  256
#define K2_ 9
#define PAD_ 2
#define DIL_ 2
#define CK_ (C_ * K2_)            // 2304
#define HW_ (H_ * W_)             // 4096
#define OUT_MAIN (B_ * O_ * HW_)  // 4194304
#define DW_ELEMS (O_ * C_ * K2_)  // 589824

#define SWZ(off) ((off) ^ (((off) >> 3) & 0x70))

// ---------------------------------------------------------------------------
// Scratch (device globals; no allocation allowed)
// ---------------------------------------------------------------------------
__device__ float g_off[B_ * 18 * HW_];            // clipped offsets (B,18,H,W)
__device__ float g_xT[B_ * HW_ * C_];             // x transposed: [b][hw][c]
__device__ unsigned char g_w[36 * 65536];         // deform_w bf16 hi/lo tiles, pre-swizzled
__device__ unsigned char g_ow[36 * 8192];         // offset_w bf16 hi/lo tiles (32x64), pre-swizzled

// ---------------------------------------------------------------------------
// helpers
// ---------------------------------------------------------------------------
__device__ __forceinline__ void ldsm4(uint32_t* r, uint32_t addr) {
    asm volatile("ldmatrix.sync.aligned.m8n8.x4.shared.b16 {%0,%1,%2,%3}, [%4];"
        : "=r"(r[0]), "=r"(r[1]), "=r"(r[2]), "=r"(r[3]) : "r"(addr));
}
__device__ __forceinline__ void mma16816(float* c, const uint32_t* a, const uint32_t* b) {
    asm volatile("mma.sync.aligned.m16n8k16.row.col.f32.bf16.bf16.f32 "
        "{%0,%1,%2,%3}, {%4,%5,%6,%7}, {%8,%9}, {%0,%1,%2,%3};"
        : "+f"(c[0]), "+f"(c[1]), "+f"(c[2]), "+f"(c[3])
        : "r"(a[0]), "r"(a[1]), "r"(a[2]), "r"(a[3]), "r"(b[0]), "r"(b[1]));
}
__device__ __forceinline__ uint32_t smem_u32(const void* p) {
    uint32_t a;
    asm("{ .reg .u64 t; cvta.to.shared.u64 t, %1; cvt.u32.u64 %0, t; }"
        : "=r"(a) : "l"(p));
    return a;
}
__device__ __forceinline__ uint32_t pack_bf16(float a, float b) {
    return ((uint32_t)__bfloat16_as_ushort(__float2bfloat16(b)) << 16) |
           (uint32_t)__bfloat16_as_ushort(__float2bfloat16(a));
}
__device__ __forceinline__ void cpasync16(uint32_t dst, const void* src) {
    asm volatile("cp.async.cg.shared.global [%0], [%1], 16;"
        :: "r"(dst), "l"(src) : "memory");
}

// ---------------------------------------------------------------------------
// Prologue kernel (pure memory): roles by blockIdx.x (256 threads each)
//   [0,4096)      : transpose x -> g_xT (32x32 tiles)
//   [4096,6400)   : deform_w prep (bf16 hi/lo, pre-swizzled) + tail copy
//   [6400,6688)   : offset_w prep (bf16 hi/lo 32x64 tiles, rows>=18 zero)
// ---------------------------------------------------------------------------
#define NB_T  4096
#define NB_P  2304
#define NB_W  288

__global__ __launch_bounds__(256) void prologue_kernel(
    const float* __restrict__ x, const float* __restrict__ ow,
    const float* __restrict__ dw, float* __restrict__ out_tail)
{
    const int bid = blockIdx.x;
    const int tid = threadIdx.x;

    if (bid < NB_T) {
        // ---- transpose ----
        __shared__ float ts[32][33];
        const int b = bid >> 10;
        const int tile = bid & 1023;
        const int c0 = (tile >> 7) * 32;
        const int hw0 = (tile & 127) * 32;
        const int tx = tid & 31, ty = tid >> 5;
        const float* xb = x + (size_t)b * C_ * HW_;
#pragma unroll
        for (int i = 0; i < 4; i++)
            ts[ty + i * 8][tx] = __ldg(xb + (size_t)(c0 + ty + i * 8) * HW_ + hw0 + tx);
        __syncthreads();
        float* dst = g_xT + (size_t)b * HW_ * C_;
#pragma unroll
        for (int i = 0; i < 4; i++)
            dst[(size_t)(hw0 + ty + i * 8) * C_ + c0 + tx] = ts[tx][ty + i * 8];
        return;
    }

    if (bid < NB_T + NB_P) {
        // ---- deform_w prep + tail copy ----
        int id = (bid - NB_T) * 256 + tid;
        out_tail[id] = dw[id];
        int k = id & 63;
        int o = (id >> 6) & 255;
        int t = id >> 14;            // 0..35
        int n = t >> 2;
        int cc = t & 3;
        int c = cc * 64 + k;
        float v = __ldg(dw + o * CK_ + c * 9 + n);
        __nv_bfloat16 hi = __float2bfloat16(v);
        __nv_bfloat16 lo = __float2bfloat16(v - __bfloat162float(hi));
        uint32_t sw = SWZ((uint32_t)(o * 128 + k * 2));
        size_t base = (size_t)t * 65536;
        *(__nv_bfloat16*)(g_w + base + sw)         = hi;
        *(__nv_bfloat16*)(g_w + base + 32768 + sw) = lo;
        return;
    }

    // ---- offset_w prep: 36 tiles x 32 rows x 64 k ----
    {
        int id = (bid - NB_T - NB_P) * 256 + tid;   // < 73728
        int k   = id & 63;
        int row = (id >> 6) & 31;
        int t   = id >> 11;          // 0..35
        float v = 0.f;
        if (row < 18)
            v = __ldg(ow + row * CK_ + ((t & 3) * 64 + k) * 9 + (t >> 2));
        __nv_bfloat16 hi = __float2bfloat16(v);
        __nv_bfloat16 lo = __float2bfloat16(v - __bfloat162float(hi));
        uint32_t sw = SWZ((uint32_t)(row * 128 + k * 2));
        size_t base = (size_t)t * 8192;
        *(__nv_bfloat16*)(g_ow + base + sw)        = hi;
        *(__nv_bfloat16*)(g_ow + base + 4096 + sw) = lo;
    }
}

// ---------------------------------------------------------------------------
// Fused kernel: [phase 0: offset conv for OWN (b,h2) via MMA] ->
// [sampling metadata] -> [R6 bf16-split GEMM mainloop] -> epilogue.
// Phase 0 is legal in-block: g_off of (b,h2) is consumed only by (b,h2).
// ---------------------------------------------------------------------------
#define OFF_A    0        // 2 buf x [2 comp][256][64] bf16 = 2 x 65536
#define OFF_B    131072   // 2 buf x [2 comp][128][64] bf16 = 2 x 32768
#define OFF_SWT  196608   // float [9*128][4]  = 18432
#define OFF_SIDX 215040   // short [9*128][4]  = 9216
#define FUSED_SMEM 224256

__global__ __launch_bounds__(512, 1) void fused_deform_mma_kernel(
    const float* __restrict__ x, const float* __restrict__ ob,
    const float* __restrict__ db, float* __restrict__ out)
{
    extern __shared__ char smem[];
    const uint32_t sb = smem_u32(smem);
    const int tid = threadIdx.x;
    const int wid = tid >> 5;
    const int lid = tid & 31;
    const int b  = blockIdx.x >> 5;
    const int h2 = blockIdx.x & 31;

    // ============ Phase 0: offset conv via bf16-split MMA (own pixels) ======
    {
        // A hi [0,4096) lo [4096,8192); B hi [8192,24576) lo [24576,40960)
        const int mtO = wid & 1;             // used by wid<8
        const int nbO = (wid >> 1) * 32;
        const int aRowO = mtO * 16 + (lid & 15);
        const int aKadO = (lid >> 4) * 16;
        const int bRowO = nbO + ((lid >> 4) & 1) * 8 + (lid & 7);
        const int bKadO = ((lid >> 3) & 1) * 16;

        float accO[4][4];
#pragma unroll
        for (int j = 0; j < 4; j++)
#pragma unroll
            for (int q = 0; q < 4; q++) accO[j][q] = 0.0f;

        for (int t = 0; t < 36; t++) {
            const int n  = t >> 2;
            const int c0 = (t & 3) * 64;
            const int dy = n / 3 - 1;
            const int dx = n % 3 - 1;
            __syncthreads();

            // A: linear 8KB copy of pre-swizzled hi+lo tile
            ((uint4*)smem)[tid] = ((const uint4*)(g_ow + (size_t)t * 8192))[tid];

            // B: im2col, lanes along pixels (coalesced)
#pragma unroll
            for (int it = 0; it < 4; it++) {
                int id = tid + it * 512;          // 2048 tasks
                int p  = id & 127;
                int c4 = (id >> 7) & 15;
                int h = h2 * 2 + (p >> 6);
                int w = p & 63;
                int yy = h + dy, xx = w + dx;
                bool ok = (yy >= 0) & (yy < H_) & (xx >= 0) & (xx < W_);
                const float* xp = x + ((size_t)b * C_ + c0 + c4 * 4) * HW_
                                    + yy * W_ + xx;
                float s0 = ok ? __ldg(xp)           : 0.f;
                float s1 = ok ? __ldg(xp + HW_)     : 0.f;
                float s2 = ok ? __ldg(xp + 2 * HW_) : 0.f;
                float s3 = ok ? __ldg(xp + 3 * HW_) : 0.f;
                uint32_t h0 = pack_bf16(s0, s1), h1 = pack_bf16(s2, s3);
                float r0 = s0 - __bfloat162float(__float2bfloat16(s0));
                float r1 = s1 - __bfloat162float(__float2bfloat16(s1));
                float r2 = s2 - __bfloat162float(__float2bfloat16(s2));
                float r3 = s3 - __bfloat162float(__float2bfloat16(s3));
                uint32_t l0 = pack_bf16(r0, r1), l1 = pack_bf16(r2, r3);
                uint32_t sw = SWZ((uint32_t)(p * 128 + c4 * 8));
                *(uint2*)(smem + 8192  + sw) = make_uint2(h0, h1);
                *(uint2*)(smem + 24576 + sw) = make_uint2(l0, l1);
            }
            __syncthreads();

            if (wid < 8) {
#pragma unroll
                for (int ks = 0; ks < 4; ks++) {
                    uint32_t bh[8], bl[8];
#pragma unroll
                    for (int pair = 0; pair < 2; pair++) {
                        uint32_t off = SWZ((uint32_t)((bRowO + pair * 16) * 128 + ks * 32 + bKadO));
                        ldsm4(bh + pair * 4, sb + 8192  + off);
                        ldsm4(bl + pair * 4, sb + 24576 + off);
                    }
                    uint32_t offA = SWZ((uint32_t)(aRowO * 128 + ks * 32 + aKadO));
                    uint32_t ah[4], al[4];
                    ldsm4(ah, sb + offA);
                    ldsm4(al, sb + 4096 + offA);
#pragma unroll
                    for (int j = 0; j < 4; j++) {
                        mma16816(accO[j], ah, bh + j * 2);
                        mma16816(accO[j], ah, bl + j * 2);
                        mma16816(accO[j], al, bh + j * 2);
                    }
                }
            }
        }

        // epilogue: bias + clip -> g_off (rows >= 18 discarded)
        if (wid < 8) {
#pragma unroll
            for (int j = 0; j < 4; j++) {
#pragma unroll
                for (int q = 0; q < 4; q++) {
                    int ch = mtO * 16 + (lid >> 2) + ((q >> 1) * 8);
                    int px = nbO + j * 8 + (lid & 3) * 2 + (q & 1);
                    if (ch < 18) {
                        float s = accO[j][q] + __ldg(ob + ch);
                        s = fminf(fmaxf(s, -1.0f), 1.0f);
                        g_off[((size_t)b * 18 + ch) * HW_
                              + (h2 * 2 + (px >> 6)) * W_ + (px & 63)] = s;
                    }
                }
            }
        }
        __syncthreads();   // g_off writes visible block-wide (same SM L1)
    }

    // ============ Phase 1: sampling metadata (reads own g_off) ==============
    float* swt  = (float*)(smem + OFF_SWT);
    short* sidx = (short*)(smem + OFF_SIDX);
    for (int task = tid; task < 9 * 128; task += 512) {
        int n = task >> 7;
        int p = task & 127;
        int h = h2 * 2 + (p >> 6);
        int w = p & 63;
        float dy = g_off[((size_t)b * 18 + 2 * n)     * HW_ + h * W_ + w];
        float dx = g_off[((size_t)b * 18 + 2 * n + 1) * HW_ + h * W_ + w];
        float py = dy + (float)(-PAD_ + (n / 3) * DIL_ + h);
        float px = dx + (float)(-PAD_ + (n % 3) * DIL_ + w);
        float y0f = floorf(py);
        float x0f = floorf(px);
        float ly1 = py - y0f, lx1 = px - x0f;
        float ly0 = 1.0f - ly1, lx0 = 1.0f - lx1;
        int y0 = (int)y0f, x0 = (int)x0f;
#pragma unroll
        for (int j = 0; j < 4; j++) {
            int yy = y0 + (j >> 1);
            int xx = x0 + (j & 1);
            float wgt = ((j >> 1) ? ly1 : ly0) * ((j & 1) ? lx1 : lx0);
            bool ok = (yy >= 0) & (yy < H_) & (xx >= 0) & (xx < W_);
            int yi = min(max(yy, 0), H_ - 1);
            int xi = min(max(xx, 0), W_ - 1);
            sidx[task * 4 + j] = (short)(yi * W_ + xi);
            swt [task * 4 + j] = ok ? wgt : 0.0f;
        }
    }
    __syncthreads();

    // ============ Phase 2: R6 bf16-split GEMM mainloop ======================
    const float* xT = g_xT + (size_t)b * HW_ * C_;
    const int ch4 = tid & 15;
    const int pixB = tid >> 4;

    const int wm = wid >> 2;
    const int wn = wid & 3;
    const int aRow = wm * 64 + (lid & 15);
    const int aKad = (lid >> 4) * 16;
    const int bRow = wn * 32 + ((lid >> 4) & 1) * 8 + (lid & 7);
    const int bKad = ((lid >> 3) & 1) * 16;

    float acc[4][4][4];
#pragma unroll
    for (int i = 0; i < 4; i++)
#pragma unroll
        for (int j = 0; j < 4; j++)
#pragma unroll
            for (int q = 0; q < 4; q++) acc[i][j][q] = 0.0f;

    // prologue: stage chunk 0
    {
        uint32_t dstA = sb + OFF_A;
        const char* srcA = (const char*)g_w;
#pragma unroll
        for (int i = 0; i < 8; i++)
            cpasync16(dstA + (tid + i * 512) * 16, srcA + (size_t)(tid + i * 512) * 16);
        asm volatile("cp.async.commit_group;" ::: "memory");
#pragma unroll
        for (int ph = 0; ph < 4; ph++) {
            int id = tid + ph * 512;
            int c4 = id & 15;
            int p  = id >> 4;
            const float4 wt = *(const float4*)(swt + p * 4);
            const short* si = sidx + p * 4;
            const float* xb = xT + c4 * 4;
            float4 v0 = __ldg((const float4*)(xb + ((int)si[0] << 8)));
            float4 v1 = __ldg((const float4*)(xb + ((int)si[1] << 8)));
            float4 v2 = __ldg((const float4*)(xb + ((int)si[2] << 8)));
            float4 v3 = __ldg((const float4*)(xb + ((int)si[3] << 8)));
            float s0 = wt.x * v0.x + wt.y * v1.x + wt.z * v2.x + wt.w * v3.x;
            float s1 = wt.x * v0.y + wt.y * v1.y + wt.z * v2.y + wt.w * v3.y;
            float s2 = wt.x * v0.z + wt.y * v1.z + wt.z * v2.z + wt.w * v3.z;
            float s3 = wt.x * v0.w + wt.y * v1.w + wt.z * v2.w + wt.w * v3.w;
            uint32_t h0 = pack_bf16(s0, s1), h1 = pack_bf16(s2, s3);
            float r0 = s0 - __bfloat162float(__float2bfloat16(s0));
            float r1 = s1 - __bfloat162float(__float2bfloat16(s1));
            float r2 = s2 - __bfloat162float(__float2bfloat16(s2));
            float r3 = s3 - __bfloat162float(__float2bfloat16(s3));
            uint32_t l0 = pack_bf16(r0, r1), l1 = pack_bf16(r2, r3);
            uint32_t sw = SWZ((uint32_t)(p * 128 + c4 * 8));
            *(uint2*)(smem + OFF_B + sw)         = make_uint2(h0, h1);
            *(uint2*)(smem + OFF_B + 16384 + sw) = make_uint2(l0, l1);
        }
    }

    for (int t = 0; t < 36; t++) {
        const uint32_t bufT = (uint32_t)(t & 1);
        const uint32_t bufN = bufT ^ 1;
        const bool more = (t < 35);

        __syncthreads();   // bar1: old-buffer reads complete

        if (more) {
            uint32_t dstA = sb + OFF_A + bufN * 65536;
            const char* srcA = (const char*)(g_w + (size_t)(t + 1) * 65536);
#pragma unroll
            for (int i = 0; i < 8; i++)
                cpasync16(dstA + (tid + i * 512) * 16, srcA + (size_t)(tid + i * 512) * 16);
            asm volatile("cp.async.commit_group;" ::: "memory");
            asm volatile("cp.async.wait_group 1;" ::: "memory");
        } else {
            asm volatile("cp.async.wait_group 0;" ::: "memory");
        }

        __syncthreads();   // bar2: A(t) landed everywhere; B(t) visible

        const uint32_t aBaseH = sb + OFF_A + bufT * 65536;
        const uint32_t aBaseL = aBaseH + 32768;
        const uint32_t bBaseH = sb + OFF_B + bufT * 32768;
        const uint32_t bBaseL = bBaseH + 16384;
        char* bDst = smem + OFF_B + bufN * 32768;

        const int nN = (t + 1) >> 2;
        const int cN = ((t + 1) & 3) * 64;

#pragma unroll
        for (int ph = 0; ph < 4; ph++) {
            float4 v0, v1, v2, v3; float4 wt;
            int p = (pixB + ph * 32) & 127;
            if (more) {
                int task = nN * 128 + p;
                wt = *(const float4*)(swt + task * 4);
                const short* si = sidx + task * 4;
                const float* xb = xT + cN + ch4 * 4;
                v0 = __ldg((const float4*)(xb + ((int)si[0] << 8)));
                v1 = __ldg((const float4*)(xb + ((int)si[1] << 8)));
                v2 = __ldg((const float4*)(xb + ((int)si[2] << 8)));
                v3 = __ldg((const float4*)(xb + ((int)si[3] << 8)));
            }

            // MMA k-step ph of chunk t
            {
                uint32_t bh[8], bl[8];
#pragma unroll
                for (int pair = 0; pair < 2; pair++) {
                    uint32_t off = SWZ((uint32_t)((bRow + pair * 16) * 128 + ph * 32 + bKad));
                    ldsm4(bh + pair * 4, bBaseH + off);
                    ldsm4(bl + pair * 4, bBaseL + off);
                }
#pragma unroll
                for (int mt = 0; mt < 4; mt++) {
                    uint32_t offA = SWZ((uint32_t)((aRow + mt * 16) * 128 + ph * 32 + aKad));
                    uint32_t ah[4], al[4];
                    ldsm4(ah, aBaseH + offA);
#pragma unroll
                    for (int j = 0; j < 4; j++) {
                        mma16816(acc[mt][j], ah, bh + j * 2);
                        mma16816(acc[mt][j], ah, bl + j * 2);
                    }
                    ldsm4(al, aBaseL + offA);
#pragma unroll
                    for (int j = 0; j < 4; j++)
                        mma16816(acc[mt][j], al, bh + j * 2);
                }
            }

            if (more) {
                float s0 = wt.x * v0.x + wt.y * v1.x + wt.z * v2.x + wt.w * v3.x;
                float s1 = wt.x * v0.y + wt.y * v1.y + wt.z * v2.y + wt.w * v3.y;
                float s2 = wt.x * v0.z + wt.y * v1.z + wt.z * v2.z + wt.w * v3.z;
                float s3 = wt.x * v0.w + wt.y * v1.w + wt.z * v2.w + wt.w * v3.w;
                uint32_t h0 = pack_bf16(s0, s1), h1 = pack_bf16(s2, s3);
                float r0 = s0 - __bfloat162float(__float2bfloat16(s0));
                float r1 = s1 - __bfloat162float(__float2bfloat16(s1));
                float r2 = s2 - __bfloat162float(__float2bfloat16(s2));
                float r3 = s3 - __bfloat162float(__float2bfloat16(s3));
                uint32_t l0 = pack_bf16(r0, r1), l1 = pack_bf16(r2, r3);
                uint32_t sw = SWZ((uint32_t)(p * 128 + ch4 * 8));
                *(uint2*)(bDst + sw)         = make_uint2(h0, h1);
                *(uint2*)(bDst + 16384 + sw) = make_uint2(l0, l1);
            }
        }
    }

    // ---- epilogue: bias + store ----
#pragma unroll
    for (int mt = 0; mt < 4; mt++) {
        int o0 = wm * 64 + mt * 16 + (lid >> 2);
        float b0v = __ldg(db + o0);
        float b1v = __ldg(db + o0 + 8);
#pragma unroll
        for (int j = 0; j < 4; j++) {
            int pixel = wn * 32 + j * 8 + (lid & 3) * 2;
            int row = pixel >> 6, col = pixel & 63;
            float* p0 = out + ((size_t)(b * O_ + o0)) * HW_
                            + (size_t)(h2 * 2 + row) * W_ + col;
            *(float2*)p0 = make_float2(acc[mt][j][0] + b0v, acc[mt][j][1] + b0v);
            float* p1 = p0 + (size_t)8 * HW_;
            *(float2*)p1 = make_float2(acc[mt][j][2] + b1v, acc[mt][j][3] + b1v);
        }
    }
}

// ---------------------------------------------------------------------------
extern "C" void kernel_launch(void* const* d_in, const int* in_sizes, int n_in,
                              void* d_out, int out_size)
{
    const float* x  = (const float*)d_in[0];
    const float* ow = (const float*)d_in[1];
    const float* ob = (const float*)d_in[2];
    const float* dw = (const float*)d_in[3];
    const float* db = (const float*)d_in[4];
    float* out = (float*)d_out;

    cudaFuncSetAttribute(fused_deform_mma_kernel,
                         cudaFuncAttributeMaxDynamicSharedMemorySize, FUSED_SMEM);

    prologue_kernel<<<NB_T + NB_P + NB_W, 256>>>(x, ow, dw, out + OUT_MAIN);
    fused_deform_mma_kernel<<<B_ * 32, 512, FUSED_SMEM>>>(x, ob, db, out);
}